// round 4
// baseline (speedup 1.0000x reference)
#include <cuda_runtime.h>
#include <cuda_fp16.h>
#include <math.h>
#include <stdint.h>

// ---------------- problem constants ----------------
#define BB    4
#define TT    4096
#define DD    2048
#define MM    64
#define DZ    512
#define HH    16
#define DH    128
#define DFF   8192
#define BT    (BB*TT)     // 16384
#define BM_   (BB*MM)     // 256

// ---------------- device scratch ----------------
__device__ __half g_hn [BT * DD];        // LN output (fp16)
__device__ __half g_z  [BM_ * DZ];       // z (fp16)
__device__ __half g_WqT[DD * DD];        // [N=D, K=D]   K-major
__device__ __half g_WkT[DD * DZ];        // [N=D, K=Dz]
__device__ __half g_WvT[DD * DZ];
__device__ __half g_W1T[DFF * DD];       // [N=Dff, K=D]
__device__ __half g_W2T[DD * DFF];       // [N=D, K=Dff]
__device__ __half g_Q  [BT * DD];        // fp16
__device__ __half g_K  [BM_ * DD];
__device__ __half g_V  [BM_ * DD];
__device__ __half g_ctx[BT * DD];        // attention output (fp16)
__device__ __half g_G  [BT * DFF];       // gelu output (fp16)

// ---------------- helpers ----------------
__device__ __forceinline__ float gelu_exact(float x) {
    return 0.5f * x * (1.f + erff(x * 0.70710678118654752440f));
}
__device__ __forceinline__ void cp_async16(uint32_t s, const void* g) {
    asm volatile("cp.async.cg.shared.global [%0], [%1], 16;" :: "r"(s), "l"(g));
}
__device__ __forceinline__ void cp_commit() {
    asm volatile("cp.async.commit_group;");
}
template<int N> __device__ __forceinline__ void cp_wait() {
    asm volatile("cp.async.wait_group %0;" :: "n"(N));
}
__device__ __forceinline__ void ldsm4(uint32_t& r0, uint32_t& r1, uint32_t& r2, uint32_t& r3,
                                      uint32_t addr) {
    asm volatile("ldmatrix.sync.aligned.m8n8.x4.shared.b16 {%0,%1,%2,%3}, [%4];"
        : "=r"(r0), "=r"(r1), "=r"(r2), "=r"(r3) : "r"(addr));
}
__device__ __forceinline__ void mma16816(float* c,
                                         uint32_t a0, uint32_t a1, uint32_t a2, uint32_t a3,
                                         uint32_t b0, uint32_t b1) {
    asm volatile(
        "mma.sync.aligned.m16n8k16.row.col.f32.f16.f16.f32 "
        "{%0,%1,%2,%3}, {%4,%5,%6,%7}, {%8,%9}, {%0,%1,%2,%3};"
        : "+f"(c[0]), "+f"(c[1]), "+f"(c[2]), "+f"(c[3])
        : "r"(a0), "r"(a1), "r"(a2), "r"(a3), "r"(b0), "r"(b1));
}

// ---------------- elementwise fp32 -> fp16 ----------------
__global__ void to_half_kernel(const float* __restrict__ in, __half* __restrict__ out, int n4) {
    int i = blockIdx.x * blockDim.x + threadIdx.x;
    if (i < n4) {
        float4 v = ((const float4*)in)[i];
        __half2 h0 = __floats2half2_rn(v.x, v.y);
        __half2 h1 = __floats2half2_rn(v.z, v.w);
        uint2 o; o.x = *(uint32_t*)&h0; o.y = *(uint32_t*)&h1;
        ((uint2*)out)[i] = o;
    }
}

// ---------------- weight transpose + half: W[K,N] -> Wt[N,K] fp16 ----------------
__global__ __launch_bounds__(256) void transpose_half(
    const float* __restrict__ W, __half* __restrict__ Wt, int K, int N)
{
    __shared__ float t[32][33];
    int n0 = blockIdx.x * 32, k0 = blockIdx.y * 32;
    int tx = threadIdx.x, ty = threadIdx.y;   // 32 x 8
    #pragma unroll
    for (int i = 0; i < 32; i += 8)
        t[ty + i][tx] = W[(size_t)(k0 + ty + i) * N + n0 + tx];
    __syncthreads();
    #pragma unroll
    for (int i = 0; i < 32; i += 8)
        Wt[(size_t)(n0 + ty + i) * K + k0 + tx] = __float2half_rn(t[tx][ty + i]);
}

// ---------------- LayerNorm: fp32 in, fp16 out ----------------
__global__ __launch_bounds__(256) void ln_kernel(
    const float* __restrict__ h, const float* __restrict__ g,
    const float* __restrict__ b, __half* __restrict__ out)
{
    int row = blockIdx.x;
    const float4* x4 = (const float4*)(h + (size_t)row * DD);
    int tx = threadIdx.x;
    float4 v0 = x4[tx], v1 = x4[tx + 256];
    float s  = v0.x + v0.y + v0.z + v0.w + v1.x + v1.y + v1.z + v1.w;
    float s2 = v0.x*v0.x + v0.y*v0.y + v0.z*v0.z + v0.w*v0.w
             + v1.x*v1.x + v1.y*v1.y + v1.z*v1.z + v1.w*v1.w;
    int lane = tx & 31, warp = tx >> 5;
    #pragma unroll
    for (int o = 16; o; o >>= 1) {
        s  += __shfl_xor_sync(0xffffffffu, s,  o);
        s2 += __shfl_xor_sync(0xffffffffu, s2, o);
    }
    __shared__ float sh[16];
    if (lane == 0) { sh[warp] = s; sh[warp + 8] = s2; }
    __syncthreads();
    float ts = 0.f, ts2 = 0.f;
    #pragma unroll
    for (int i = 0; i < 8; i++) { ts += sh[i]; ts2 += sh[i + 8]; }
    float mu  = ts * (1.f / DD);
    float var = ts2 * (1.f / DD) - mu * mu;
    float inv = rsqrtf(var + 1e-5f);

    const float4* g4 = (const float4*)g;
    const float4* b4 = (const float4*)b;
    uint2* o4 = (uint2*)(out + (size_t)row * DD);
    #pragma unroll
    for (int half_i = 0; half_i < 2; half_i++) {
        float4 v = half_i ? v1 : v0;
        int idx = tx + half_i * 256;
        float4 ga = g4[idx], bb = b4[idx];
        float y0 = (v.x - mu) * inv * ga.x + bb.x;
        float y1 = (v.y - mu) * inv * ga.y + bb.y;
        float y2 = (v.z - mu) * inv * ga.z + bb.z;
        float y3 = (v.w - mu) * inv * ga.w + bb.w;
        __half2 h0 = __floats2half2_rn(y0, y1);
        __half2 h1 = __floats2half2_rn(y2, y3);
        uint2 o; o.x = *(uint32_t*)&h0; o.y = *(uint32_t*)&h1;
        o4[idx] = o;
    }
}

// ---------------- fp16 GEMM: C[M,N] = A[M,K] @ Bt[N,K]^T ----------------
// 128x256 block tile, 64x64 warp tile, mma m16n8k16, 4-stage cp.async.
// EPI 0: C(fp16) = acc + bias
// EPI 1: C(fp16) = gelu(acc + bias)
// EPI 2: C(fp32) = res + tanh(*alpha) * (acc + bias)
template<int EPI>
__global__ void __launch_bounds__(256, 1) gemm_fp16(
    const __half* __restrict__ A, const __half* __restrict__ Bt,
    const float* __restrict__ bias, void* __restrict__ Cv,
    int Mdim, int Ndim, int Kdim,
    const float* __restrict__ res, const float* __restrict__ alpha)
{
    constexpr int STAGE = 24576;           // 8KB A + 16KB B per stage
    extern __shared__ __align__(128) char smem[];
    uint32_t sb = (uint32_t)__cvta_generic_to_shared(smem);
    const int tid  = threadIdx.x;
    const int lane = tid & 31, warp = tid >> 5;
    const int wm = (warp & 1) * 64, wn = (warp >> 1) * 64;   // 2x4 warp grid

    // --- tile coords with grouped-M rasterization ---
    int gm = Mdim >> 7, gn = Ndim >> 8;
    int pid = blockIdx.x;
    const int GRP = 8;
    int width = GRP * gn;
    int grp = pid / width;
    int first = grp * GRP;
    int sz = min(gm - first, GRP);
    int mt = first + (pid % sz);
    int nt = (pid % width) / sz;
    const int bm = mt << 7, bn = nt << 8;

    float acc[4][8][4];
    #pragma unroll
    for (int i = 0; i < 4; i++)
        #pragma unroll
        for (int j = 0; j < 8; j++)
            #pragma unroll
            for (int k = 0; k < 4; k++) acc[i][j][k] = 0.f;

    const int KT = Kdim >> 5;   // k-tiles of 32

    // loader: 2 A-chunks + 4 B-chunks of 16B per thread per k-tile
    const int lrow = tid >> 2, lch = tid & 3;
    const uint32_t lsw = (uint32_t)(lch ^ ((lrow >> 1) & 3)) << 4;
    auto loadTile = [&](int kt) {
        uint32_t base = sb + (kt & 3) * STAGE;
        const __half* Ag = A  + (size_t)bm * Kdim + kt * 32 + lch * 8;
        const __half* Bg = Bt + (size_t)bn * Kdim + kt * 32 + lch * 8;
        cp_async16(base + lrow * 64 + lsw,        Ag + (size_t)lrow * Kdim);
        cp_async16(base + (lrow + 64) * 64 + lsw, Ag + (size_t)(lrow + 64) * Kdim);
        uint32_t bbse = base + 8192;
        #pragma unroll
        for (int i = 0; i < 4; i++)
            cp_async16(bbse + (lrow + i * 64) * 64 + lsw,
                       Bg + (size_t)(lrow + i * 64) * Kdim);
        cp_commit();
    };

    loadTile(0); loadTile(1); loadTile(2);

    // ldmatrix row indices
    const int ar0 = wm + (lane & 15);                      // A rows; +16 per mi
    const int brr = wn + (lane & 7) + ((lane >> 4) << 3);  // B base row; +16 per ni
    const int a_l16 = (lane >> 4);
    const int b_l8  = (lane >> 3) & 1;

    for (int kt = 0; kt < KT; ++kt) {
        cp_wait<2>();
        __syncthreads();
        if (kt + 3 < KT) loadTile(kt + 3); else cp_commit();

        uint32_t Ab = sb + (kt & 3) * STAGE;
        uint32_t Bb = Ab + 8192;
        #pragma unroll
        for (int ks = 0; ks < 2; ++ks) {
            uint32_t a[4][4];
            int ach = ks * 2 + a_l16;
            #pragma unroll
            for (int mi = 0; mi < 4; mi++) {
                int r = ar0 + mi * 16;
                uint32_t addr = Ab + r * 64 + (((uint32_t)(ach ^ ((r >> 1) & 3))) << 4);
                ldsm4(a[mi][0], a[mi][1], a[mi][2], a[mi][3], addr);
            }
            int bch = ks * 2 + b_l8;
            #pragma unroll
            for (int ni = 0; ni < 4; ni++) {
                int r = brr + ni * 16;
                uint32_t addr = Bb + r * 64 + (((uint32_t)(bch ^ ((r >> 1) & 3))) << 4);
                uint32_t b0, b1, b2, b3;
                ldsm4(b0, b1, b2, b3, addr);
                #pragma unroll
                for (int mi = 0; mi < 4; mi++) {
                    mma16816(acc[mi][ni * 2    ], a[mi][0], a[mi][1], a[mi][2], a[mi][3], b0, b1);
                    mma16816(acc[mi][ni * 2 + 1], a[mi][0], a[mi][1], a[mi][2], a[mi][3], b2, b3);
                }
            }
        }
    }

    // --- epilogue ---
    float ta = 0.f;
    if (EPI == 2) ta = tanhf(*alpha);
    const int r0 = bm + wm + (lane >> 2);
    const int c0 = bn + wn + (lane & 3) * 2;
    #pragma unroll
    for (int mi = 0; mi < 4; mi++) {
        #pragma unroll
        for (int nj = 0; nj < 8; nj++) {
            int col = c0 + nj * 8;
            float2 bv = *(const float2*)&bias[col];
            #pragma unroll
            for (int hf = 0; hf < 2; hf++) {
                int row = r0 + mi * 16 + hf * 8;
                float v0 = acc[mi][nj][hf * 2    ] + bv.x;
                float v1 = acc[mi][nj][hf * 2 + 1] + bv.y;
                size_t off = (size_t)row * Ndim + col;
                if (EPI == 0) {
                    __half2 hv = __floats2half2_rn(v0, v1);
                    *(__half2*)((__half*)Cv + off) = hv;
                } else if (EPI == 1) {
                    __half2 hv = __floats2half2_rn(gelu_exact(v0), gelu_exact(v1));
                    *(__half2*)((__half*)Cv + off) = hv;
                } else {
                    float2 rr = *(const float2*)&res[off];
                    float2 o; o.x = rr.x + ta * v0; o.y = rr.y + ta * v1;
                    *(float2*)((float*)Cv + off) = o;
                }
            }
        }
    }
}

// ---------------- cross-attention (M=64 keys, dh=128), fp16 in/out ----------------
__global__ __launch_bounds__(256) void attn_kernel(
    const __half* __restrict__ Q, const __half* __restrict__ Kb,
    const __half* __restrict__ Vb, __half* __restrict__ ctx)
{
    extern __shared__ float sm[];
    float* Qs = sm;                 // [64][128]
    float* Kt = Qs + 64 * 128;      // [128][64]
    float* Vs = Kt + 128 * 64;      // [64][128]
    float* ws = Vs + 64 * 128;      // [8][64]

    const int b = blockIdx.z, hh = blockIdx.y;
    const int t0 = blockIdx.x * 64;
    const int tid = threadIdx.x;

    for (int i = tid; i < MM * DH; i += 256) {
        int m = i >> 7, d = i & 127;
        size_t kvoff = (size_t)(b * MM + m) * DD + hh * DH + d;
        Kt[d * 64 + m] = __half2float(Kb[kvoff]);
        Vs[i]          = __half2float(Vb[kvoff]);
        Qs[i]          = __half2float(Q[(size_t)(b * TT + t0 + m) * DD + hh * DH + d]);
    }
    __syncthreads();

    const int warp = tid >> 5, lane = tid & 31;
    const float scale = 0.08838834764831844f;   // 1/sqrt(128)

    for (int rr = 0; rr < 8; ++rr) {
        int r = warp * 8 + rr;
        const float* qp = &Qs[r * 128];
        float s0 = 0.f, s1 = 0.f;
        #pragma unroll 8
        for (int d = 0; d < 128; ++d) {
            float q = qp[d];
            float2 kk = *(const float2*)&Kt[d * 64 + lane * 2];
            s0 = fmaf(q, kk.x, s0);
            s1 = fmaf(q, kk.y, s1);
        }
        s0 *= scale; s1 *= scale;
        float mx = fmaxf(s0, s1);
        #pragma unroll
        for (int o = 16; o; o >>= 1) mx = fmaxf(mx, __shfl_xor_sync(0xffffffffu, mx, o));
        float e0 = expf(s0 - mx), e1 = expf(s1 - mx);
        float sum = e0 + e1;
        #pragma unroll
        for (int o = 16; o; o >>= 1) sum += __shfl_xor_sync(0xffffffffu, sum, o);
        float inv = 1.f / sum;
        ws[warp * 64 + lane * 2    ] = e0 * inv;
        ws[warp * 64 + lane * 2 + 1] = e1 * inv;
        __syncwarp();

        float4 a; a.x = a.y = a.z = a.w = 0.f;
        #pragma unroll 8
        for (int m = 0; m < 64; ++m) {
            float wv = ws[warp * 64 + m];
            float4 v = *(const float4*)&Vs[m * 128 + lane * 4];
            a.x = fmaf(wv, v.x, a.x); a.y = fmaf(wv, v.y, a.y);
            a.z = fmaf(wv, v.z, a.z); a.w = fmaf(wv, v.w, a.w);
        }
        __half2 h0 = __floats2half2_rn(a.x, a.y);
        __half2 h1 = __floats2half2_rn(a.z, a.w);
        uint2 o; o.x = *(uint32_t*)&h0; o.y = *(uint32_t*)&h1;
        *(uint2*)&ctx[(size_t)(b * TT + t0 + r) * DD + hh * DH + lane * 4] = o;
        __syncwarp();
    }
}

// ---------------- launch ----------------
template<typename T>
static T* sym_addr(const void* sym) {
    void* p = nullptr;
    cudaGetSymbolAddress(&p, sym);
    return (T*)p;
}

extern "C" void kernel_launch(void* const* d_in, const int* in_sizes, int n_in,
                              void* d_out, int out_size)
{
    const float* h    = (const float*)d_in[0];
    const float* z    = (const float*)d_in[1];
    const float* ln_g = (const float*)d_in[2];
    const float* ln_b = (const float*)d_in[3];
    const float* Wq   = (const float*)d_in[4];
    const float* bq   = (const float*)d_in[5];
    const float* Wk   = (const float*)d_in[6];
    const float* bk   = (const float*)d_in[7];
    const float* Wv   = (const float*)d_in[8];
    const float* bv   = (const float*)d_in[9];
    const float* W1   = (const float*)d_in[10];
    const float* b1   = (const float*)d_in[11];
    const float* W2   = (const float*)d_in[12];
    const float* b2   = (const float*)d_in[13];
    const float* alpha= (const float*)d_in[14];
    float* out = (float*)d_out;

    __half* hn  = sym_addr<__half>(g_hn);
    __half* zr  = sym_addr<__half>(g_z);
    __half* wqT = sym_addr<__half>(g_WqT);
    __half* wkT = sym_addr<__half>(g_WkT);
    __half* wvT = sym_addr<__half>(g_WvT);
    __half* w1T = sym_addr<__half>(g_W1T);
    __half* w2T = sym_addr<__half>(g_W2T);
    __half* qb  = sym_addr<__half>(g_Q);
    __half* kb  = sym_addr<__half>(g_K);
    __half* vb  = sym_addr<__half>(g_V);
    __half* cx  = sym_addr<__half>(g_ctx);
    __half* gb  = sym_addr<__half>(g_G);

    const int SMEM = 4 * 24576;   // 96KB
    cudaFuncSetAttribute(gemm_fp16<0>, cudaFuncAttributeMaxDynamicSharedMemorySize, SMEM);
    cudaFuncSetAttribute(gemm_fp16<1>, cudaFuncAttributeMaxDynamicSharedMemorySize, SMEM);
    cudaFuncSetAttribute(gemm_fp16<2>, cudaFuncAttributeMaxDynamicSharedMemorySize, SMEM);

    // 1) weight transposes -> [N,K] fp16
    transpose_half<<<dim3(DD / 32, DD / 32),  dim3(32, 8)>>>(Wq, wqT, DD,  DD);
    transpose_half<<<dim3(DD / 32, DZ / 32),  dim3(32, 8)>>>(Wk, wkT, DZ,  DD);
    transpose_half<<<dim3(DD / 32, DZ / 32),  dim3(32, 8)>>>(Wv, wvT, DZ,  DD);
    transpose_half<<<dim3(DFF / 32, DD / 32), dim3(32, 8)>>>(W1, w1T, DD,  DFF);
    transpose_half<<<dim3(DD / 32, DFF / 32), dim3(32, 8)>>>(W2, w2T, DFF, DD);

    // 2) z -> fp16, LayerNorm h -> fp16
    to_half_kernel<<<(BM_ * DZ / 4 + 255) / 256, 256>>>(z, zr, BM_ * DZ / 4);
    ln_kernel<<<BT, 256>>>(h, ln_g, ln_b, hn);

    // 3) projections -> fp16
    gemm_fp16<0><<<(BT / 128) * (DD / 256), 256, SMEM>>>(hn, wqT, bq, qb, BT, DD, DD, nullptr, nullptr);
    gemm_fp16<0><<<(BM_ / 128) * (DD / 256), 256, SMEM>>>(zr, wkT, bk, kb, BM_, DD, DZ, nullptr, nullptr);
    gemm_fp16<0><<<(BM_ / 128) * (DD / 256), 256, SMEM>>>(zr, wvT, bv, vb, BM_, DD, DZ, nullptr, nullptr);

    // 4) cross attention -> ctx (fp16)
    {
        int smem = (3 * 64 * 128 + 8 * 64) * (int)sizeof(float);
        cudaFuncSetAttribute(attn_kernel, cudaFuncAttributeMaxDynamicSharedMemorySize, smem);
        attn_kernel<<<dim3(TT / 64, HH, BB), 256, smem>>>(qb, kb, vb, cx);
    }

    // 5) FFN1 + fused exact GELU -> fp16
    gemm_fp16<1><<<(BT / 128) * (DFF / 256), 256, SMEM>>>(cx, w1T, b1, gb, BT, DFF, DD, nullptr, nullptr);

    // 6) FFN2 + fused residual -> fp32 out
    gemm_fp16<2><<<(BT / 128) * (DD / 256), 256, SMEM>>>(gb, w2T, b2, out, BT, DD, DFF, h, alpha);
}

// round 5
// speedup vs baseline: 1.3634x; 1.3634x over previous
#include <cuda_runtime.h>
#include <cuda_fp16.h>
#include <math.h>
#include <stdint.h>

// ---------------- problem constants ----------------
#define BB    4
#define TT    4096
#define DD    2048
#define MM    64
#define DZ    512
#define HH    16
#define DH    128
#define DFF   8192
#define BT    (BB*TT)     // 16384
#define BM_   (BB*MM)     // 256

// ---------------- device scratch ----------------
__device__ __half g_hn [BT * DD];
__device__ __half g_z  [BM_ * DZ];
__device__ __half g_WqT[DD * DD];        // [N,K] K-major
__device__ __half g_WkT[DD * DZ];
__device__ __half g_WvT[DD * DZ];
__device__ __half g_W1T[DFF * DD];
__device__ __half g_W2T[DD * DFF];
__device__ __half g_Q  [BT * DD];
__device__ __half g_K  [BM_ * DD];
__device__ __half g_V  [BM_ * DD];
__device__ __half g_ctx[BT * DD];
__device__ __half g_G  [BT * DFF];

// ---------------- helpers ----------------
__device__ __forceinline__ float gelu_exact(float x) {
    return 0.5f * x * (1.f + erff(x * 0.70710678118654752440f));
}
__device__ __forceinline__ void cp_async16(uint32_t s, const void* g) {
    asm volatile("cp.async.cg.shared.global [%0], [%1], 16;" :: "r"(s), "l"(g));
}
__device__ __forceinline__ void cp_commit() {
    asm volatile("cp.async.commit_group;");
}
template<int N> __device__ __forceinline__ void cp_wait() {
    asm volatile("cp.async.wait_group %0;" :: "n"(N));
}
__device__ __forceinline__ void ldsm4(uint32_t& r0, uint32_t& r1, uint32_t& r2, uint32_t& r3,
                                      uint32_t addr) {
    asm volatile("ldmatrix.sync.aligned.m8n8.x4.shared.b16 {%0,%1,%2,%3}, [%4];"
        : "=r"(r0), "=r"(r1), "=r"(r2), "=r"(r3) : "r"(addr));
}
__device__ __forceinline__ void mma16816(float* c,
                                         uint32_t a0, uint32_t a1, uint32_t a2, uint32_t a3,
                                         uint32_t b0, uint32_t b1) {
    asm volatile(
        "mma.sync.aligned.m16n8k16.row.col.f32.f16.f16.f32 "
        "{%0,%1,%2,%3}, {%4,%5,%6,%7}, {%8,%9}, {%0,%1,%2,%3};"
        : "+f"(c[0]), "+f"(c[1]), "+f"(c[2]), "+f"(c[3])
        : "r"(a0), "r"(a1), "r"(a2), "r"(a3), "r"(b0), "r"(b1));
}

// ---------------- elementwise fp32 -> fp16 ----------------
__global__ void to_half_kernel(const float* __restrict__ in, __half* __restrict__ out, int n4) {
    int i = blockIdx.x * blockDim.x + threadIdx.x;
    if (i < n4) {
        float4 v = ((const float4*)in)[i];
        __half2 h0 = __floats2half2_rn(v.x, v.y);
        __half2 h1 = __floats2half2_rn(v.z, v.w);
        uint2 o; o.x = *(uint32_t*)&h0; o.y = *(uint32_t*)&h1;
        ((uint2*)out)[i] = o;
    }
}

// ---------------- weight transpose: W[K,N] fp32 -> Wt[N,K] fp16 ----------------
__global__ __launch_bounds__(256) void transpose_half(
    const float* __restrict__ W, __half* __restrict__ Wt, int K, int N)
{
    __shared__ float t[32][33];
    int n0 = blockIdx.x * 32, k0 = blockIdx.y * 32;
    int tx = threadIdx.x, ty = threadIdx.y;   // 32 x 8
    #pragma unroll
    for (int i = 0; i < 32; i += 8)
        t[ty + i][tx] = W[(size_t)(k0 + ty + i) * N + n0 + tx];
    __syncthreads();
    #pragma unroll
    for (int i = 0; i < 32; i += 8)
        Wt[(size_t)(n0 + ty + i) * K + k0 + tx] = __float2half_rn(t[tx][ty + i]);
}

// ---------------- LayerNorm: fp32 in, fp16 out ----------------
__global__ __launch_bounds__(256) void ln_kernel(
    const float* __restrict__ h, const float* __restrict__ g,
    const float* __restrict__ b, __half* __restrict__ out)
{
    int row = blockIdx.x;
    const float4* x4 = (const float4*)(h + (size_t)row * DD);
    int tx = threadIdx.x;
    float4 v0 = x4[tx], v1 = x4[tx + 256];
    float s  = v0.x + v0.y + v0.z + v0.w + v1.x + v1.y + v1.z + v1.w;
    float s2 = v0.x*v0.x + v0.y*v0.y + v0.z*v0.z + v0.w*v0.w
             + v1.x*v1.x + v1.y*v1.y + v1.z*v1.z + v1.w*v1.w;
    int lane = tx & 31, warp = tx >> 5;
    #pragma unroll
    for (int o = 16; o; o >>= 1) {
        s  += __shfl_xor_sync(0xffffffffu, s,  o);
        s2 += __shfl_xor_sync(0xffffffffu, s2, o);
    }
    __shared__ float sh[16];
    if (lane == 0) { sh[warp] = s; sh[warp + 8] = s2; }
    __syncthreads();
    float ts = 0.f, ts2 = 0.f;
    #pragma unroll
    for (int i = 0; i < 8; i++) { ts += sh[i]; ts2 += sh[i + 8]; }
    float mu  = ts * (1.f / DD);
    float var = ts2 * (1.f / DD) - mu * mu;
    float inv = rsqrtf(var + 1e-5f);

    const float4* g4 = (const float4*)g;
    const float4* b4 = (const float4*)b;
    uint2* o4 = (uint2*)(out + (size_t)row * DD);
    #pragma unroll
    for (int half_i = 0; half_i < 2; half_i++) {
        float4 v = half_i ? v1 : v0;
        int idx = tx + half_i * 256;
        float4 ga = g4[idx], bb = b4[idx];
        float y0 = (v.x - mu) * inv * ga.x + bb.x;
        float y1 = (v.y - mu) * inv * ga.y + bb.y;
        float y2 = (v.z - mu) * inv * ga.z + bb.z;
        float y3 = (v.w - mu) * inv * ga.w + bb.w;
        __half2 h0 = __floats2half2_rn(y0, y1);
        __half2 h1 = __floats2half2_rn(y2, y3);
        uint2 o; o.x = *(uint32_t*)&h0; o.y = *(uint32_t*)&h1;
        o4[idx] = o;
    }
}

// ---------------- fp16 GEMM: C[M,N] = A[M,K] @ Bt[N,K]^T ----------------
// 128x128 tile, 32x64 warp tile, BK=64 (128B rows, full SW128), 3 stages.
// EPI 0: C(fp16) = acc + bias
// EPI 1: C(fp16) = gelu(acc + bias)
// EPI 2: C(fp32) = res + tanh(*alpha) * (acc + bias)
template<int EPI>
__global__ void __launch_bounds__(256, 2) gemm_fp16(
    const __half* __restrict__ A, const __half* __restrict__ Bt,
    const float* __restrict__ bias, void* __restrict__ Cv,
    int Mdim, int Ndim, int Kdim,
    const float* __restrict__ res, const float* __restrict__ alpha)
{
    constexpr int STAGE = 32768;           // 16KB A + 16KB B (128 rows x 128B each)
    extern __shared__ __align__(128) char smem[];
    uint32_t sb = (uint32_t)__cvta_generic_to_shared(smem);
    const int tid  = threadIdx.x;
    const int lane = tid & 31, warp = tid >> 5;
    const int wm = (warp & 3) * 32, wn = (warp >> 2) * 64;   // 4x2 warp grid

    // --- tile coords with grouped-M rasterization ---
    int gm = Mdim >> 7, gn = Ndim >> 7;
    int pid = blockIdx.x;
    const int GRP = 8;
    int width = GRP * gn;
    int grp = pid / width;
    int first = grp * GRP;
    int sz = min(gm - first, GRP);
    int mt = first + (pid % sz);
    int nt = (pid % width) / sz;
    const int bm = mt << 7, bn = nt << 7;

    float acc[2][8][4];
    #pragma unroll
    for (int i = 0; i < 2; i++)
        #pragma unroll
        for (int j = 0; j < 8; j++)
            #pragma unroll
            for (int k = 0; k < 4; k++) acc[i][j][k] = 0.f;

    const int KT = Kdim >> 6;   // k-tiles of 64

    // loader: 4 A-chunks + 4 B-chunks of 16B per thread per k-tile
    const int lrow = tid >> 3, lch = tid & 7;          // rows 0..31, chunks 0..7
    auto loadTile = [&](int kt, int st) {
        uint32_t base = sb + st * STAGE;
        const __half* Ag = A  + (size_t)bm * Kdim + kt * 64 + lch * 8;
        const __half* Bg = Bt + (size_t)bn * Kdim + kt * 64 + lch * 8;
        #pragma unroll
        for (int i = 0; i < 4; i++) {
            int r = lrow + i * 32;
            uint32_t sw = (uint32_t)(lch ^ (r & 7)) << 4;
            cp_async16(base + r * 128 + sw,         Ag + (size_t)r * Kdim);
            cp_async16(base + 16384 + r * 128 + sw, Bg + (size_t)r * Kdim);
        }
        cp_commit();
    };

    loadTile(0, 0); loadTile(1, 1);

    // ldmatrix row indices
    const int ar0 = wm + (lane & 15);                      // A rows; +16 for mi=1
    const int brr = wn + (lane & 7) + ((lane >> 4) << 3);  // B base row; +16 per ni
    const int a_l16 = (lane >> 4);
    const int b_l8  = (lane >> 3) & 1;

    int st = 0;
    for (int kt = 0; kt < KT; ++kt) {
        cp_wait<1>();
        __syncthreads();
        if (kt + 2 < KT) {
            int nst = st + 2; if (nst >= 3) nst -= 3;
            loadTile(kt + 2, nst);
        } else {
            cp_commit();
        }

        uint32_t Ab = sb + st * STAGE;
        uint32_t Bb = Ab + 16384;
        #pragma unroll
        for (int ks = 0; ks < 4; ++ks) {
            uint32_t a[2][4];
            int ach = ks * 2 + a_l16;
            #pragma unroll
            for (int mi = 0; mi < 2; mi++) {
                int r = ar0 + mi * 16;
                uint32_t addr = Ab + r * 128 + (((uint32_t)(ach ^ (r & 7))) << 4);
                ldsm4(a[mi][0], a[mi][1], a[mi][2], a[mi][3], addr);
            }
            int bch = ks * 2 + b_l8;
            #pragma unroll
            for (int ni = 0; ni < 4; ni++) {
                int r = brr + ni * 16;
                uint32_t addr = Bb + r * 128 + (((uint32_t)(bch ^ (r & 7))) << 4);
                uint32_t b0, b1, b2, b3;
                ldsm4(b0, b1, b2, b3, addr);
                #pragma unroll
                for (int mi = 0; mi < 2; mi++) {
                    mma16816(acc[mi][ni * 2    ], a[mi][0], a[mi][1], a[mi][2], a[mi][3], b0, b1);
                    mma16816(acc[mi][ni * 2 + 1], a[mi][0], a[mi][1], a[mi][2], a[mi][3], b2, b3);
                }
            }
        }
        if (++st == 3) st = 0;
    }

    // --- epilogue ---
    float ta = 0.f;
    if (EPI == 2) ta = tanhf(*alpha);
    const int r0 = bm + wm + (lane >> 2);
    const int c0 = bn + wn + (lane & 3) * 2;
    #pragma unroll
    for (int mi = 0; mi < 2; mi++) {
        #pragma unroll
        for (int nj = 0; nj < 8; nj++) {
            int col = c0 + nj * 8;
            float2 bv = *(const float2*)&bias[col];
            #pragma unroll
            for (int hf = 0; hf < 2; hf++) {
                int row = r0 + mi * 16 + hf * 8;
                float v0 = acc[mi][nj][hf * 2    ] + bv.x;
                float v1 = acc[mi][nj][hf * 2 + 1] + bv.y;
                size_t off = (size_t)row * Ndim + col;
                if (EPI == 0) {
                    __half2 hv = __floats2half2_rn(v0, v1);
                    *(__half2*)((__half*)Cv + off) = hv;
                } else if (EPI == 1) {
                    __half2 hv = __floats2half2_rn(gelu_exact(v0), gelu_exact(v1));
                    *(__half2*)((__half*)Cv + off) = hv;
                } else {
                    float2 rr = *(const float2*)&res[off];
                    float2 o; o.x = rr.x + ta * v0; o.y = rr.y + ta * v1;
                    *(float2*)((float*)Cv + off) = o;
                }
            }
        }
    }
}

// ---------------- cross-attention (M=64 keys, dh=128), fp16 in/out ----------------
// 4 rows per pass per warp: K/V smem reads amortized 4x.
__global__ __launch_bounds__(256) void attn_kernel(
    const __half* __restrict__ Q, const __half* __restrict__ Kb,
    const __half* __restrict__ Vb, __half* __restrict__ ctx)
{
    extern __shared__ float sm[];
    float* Qs = sm;                 // [64][128]
    float* Kt = Qs + 64 * 128;      // [128][64]  d-major
    float* Vs = Kt + 128 * 64;      // [64][128]
    float* ws = Vs + 64 * 128;      // [8 warps][4 rows][64]... use [8][256]

    const int b = blockIdx.z, hh = blockIdx.y;
    const int t0 = blockIdx.x * 64;
    const int tid = threadIdx.x;

    for (int i = tid; i < MM * DH; i += 256) {
        int m = i >> 7, d = i & 127;
        size_t kvoff = (size_t)(b * MM + m) * DD + hh * DH + d;
        Kt[d * 64 + m] = __half2float(Kb[kvoff]);
        Vs[i]          = __half2float(Vb[kvoff]);
        Qs[i]          = __half2float(Q[(size_t)(b * TT + t0 + m) * DD + hh * DH + d]);
    }
    __syncthreads();

    const int warp = tid >> 5, lane = tid & 31;
    float* wsw = ws + warp * 256;
    const float scale = 0.08838834764831844f;   // 1/sqrt(128)

    #pragma unroll
    for (int g = 0; g < 2; ++g) {
        int r = warp * 8 + g * 4;
        float s[4][2];
        #pragma unroll
        for (int i = 0; i < 4; i++) s[i][0] = s[i][1] = 0.f;
        const float* q0 = &Qs[(r + 0) * 128];
        const float* q1 = &Qs[(r + 1) * 128];
        const float* q2 = &Qs[(r + 2) * 128];
        const float* q3 = &Qs[(r + 3) * 128];
        #pragma unroll 4
        for (int d = 0; d < 128; ++d) {
            float2 kk = *(const float2*)&Kt[d * 64 + lane * 2];
            float a0 = q0[d], a1 = q1[d], a2 = q2[d], a3 = q3[d];
            s[0][0] = fmaf(a0, kk.x, s[0][0]); s[0][1] = fmaf(a0, kk.y, s[0][1]);
            s[1][0] = fmaf(a1, kk.x, s[1][0]); s[1][1] = fmaf(a1, kk.y, s[1][1]);
            s[2][0] = fmaf(a2, kk.x, s[2][0]); s[2][1] = fmaf(a2, kk.y, s[2][1]);
            s[3][0] = fmaf(a3, kk.x, s[3][0]); s[3][1] = fmaf(a3, kk.y, s[3][1]);
        }
        #pragma unroll
        for (int i = 0; i < 4; i++) {
            float s0 = s[i][0] * scale, s1 = s[i][1] * scale;
            float mx = fmaxf(s0, s1);
            #pragma unroll
            for (int o = 16; o; o >>= 1) mx = fmaxf(mx, __shfl_xor_sync(0xffffffffu, mx, o));
            float e0 = expf(s0 - mx), e1 = expf(s1 - mx);
            float sum = e0 + e1;
            #pragma unroll
            for (int o = 16; o; o >>= 1) sum += __shfl_xor_sync(0xffffffffu, sum, o);
            float inv = 1.f / sum;
            wsw[i * 64 + lane * 2    ] = e0 * inv;
            wsw[i * 64 + lane * 2 + 1] = e1 * inv;
        }
        __syncwarp();

        float4 a0, a1, a2, a3;
        a0.x = a0.y = a0.z = a0.w = 0.f;
        a1 = a0; a2 = a0; a3 = a0;
        #pragma unroll 4
        for (int m = 0; m < 64; ++m) {
            float4 v = *(const float4*)&Vs[m * 128 + lane * 4];
            float w0 = wsw[0 * 64 + m], w1 = wsw[1 * 64 + m];
            float w2 = wsw[2 * 64 + m], w3 = wsw[3 * 64 + m];
            a0.x = fmaf(w0, v.x, a0.x); a0.y = fmaf(w0, v.y, a0.y);
            a0.z = fmaf(w0, v.z, a0.z); a0.w = fmaf(w0, v.w, a0.w);
            a1.x = fmaf(w1, v.x, a1.x); a1.y = fmaf(w1, v.y, a1.y);
            a1.z = fmaf(w1, v.z, a1.z); a1.w = fmaf(w1, v.w, a1.w);
            a2.x = fmaf(w2, v.x, a2.x); a2.y = fmaf(w2, v.y, a2.y);
            a2.z = fmaf(w2, v.z, a2.z); a2.w = fmaf(w2, v.w, a2.w);
            a3.x = fmaf(w3, v.x, a3.x); a3.y = fmaf(w3, v.y, a3.y);
            a3.z = fmaf(w3, v.z, a3.z); a3.w = fmaf(w3, v.w, a3.w);
        }
        #pragma unroll
        for (int i = 0; i < 4; i++) {
            float4 a = (i == 0) ? a0 : (i == 1) ? a1 : (i == 2) ? a2 : a3;
            __half2 h0 = __floats2half2_rn(a.x, a.y);
            __half2 h1 = __floats2half2_rn(a.z, a.w);
            uint2 o; o.x = *(uint32_t*)&h0; o.y = *(uint32_t*)&h1;
            *(uint2*)&ctx[(size_t)(b * TT + t0 + r + i) * DD + hh * DH + lane * 4] = o;
        }
        __syncwarp();
    }
}

// ---------------- launch ----------------
template<typename T>
static T* sym_addr(const void* sym) {
    void* p = nullptr;
    cudaGetSymbolAddress(&p, sym);
    return (T*)p;
}

extern "C" void kernel_launch(void* const* d_in, const int* in_sizes, int n_in,
                              void* d_out, int out_size)
{
    const float* h    = (const float*)d_in[0];
    const float* z    = (const float*)d_in[1];
    const float* ln_g = (const float*)d_in[2];
    const float* ln_b = (const float*)d_in[3];
    const float* Wq   = (const float*)d_in[4];
    const float* bq   = (const float*)d_in[5];
    const float* Wk   = (const float*)d_in[6];
    const float* bk   = (const float*)d_in[7];
    const float* Wv   = (const float*)d_in[8];
    const float* bv   = (const float*)d_in[9];
    const float* W1   = (const float*)d_in[10];
    const float* b1   = (const float*)d_in[11];
    const float* W2   = (const float*)d_in[12];
    const float* b2   = (const float*)d_in[13];
    const float* alpha= (const float*)d_in[14];
    float* out = (float*)d_out;

    __half* hn  = sym_addr<__half>(g_hn);
    __half* zr  = sym_addr<__half>(g_z);
    __half* wqT = sym_addr<__half>(g_WqT);
    __half* wkT = sym_addr<__half>(g_WkT);
    __half* wvT = sym_addr<__half>(g_WvT);
    __half* w1T = sym_addr<__half>(g_W1T);
    __half* w2T = sym_addr<__half>(g_W2T);
    __half* qb  = sym_addr<__half>(g_Q);
    __half* kb  = sym_addr<__half>(g_K);
    __half* vb  = sym_addr<__half>(g_V);
    __half* cx  = sym_addr<__half>(g_ctx);
    __half* gb  = sym_addr<__half>(g_G);

    const int SMEM = 3 * 32768;   // 96KB, 2 CTA/SM
    cudaFuncSetAttribute(gemm_fp16<0>, cudaFuncAttributeMaxDynamicSharedMemorySize, SMEM);
    cudaFuncSetAttribute(gemm_fp16<1>, cudaFuncAttributeMaxDynamicSharedMemorySize, SMEM);
    cudaFuncSetAttribute(gemm_fp16<2>, cudaFuncAttributeMaxDynamicSharedMemorySize, SMEM);

    // launches ordered so that launch index 5 (ncu -s 5 -c 1) = Q-projection GEMM
    ln_kernel<<<BT, 256>>>(h, ln_g, ln_b, hn);                                      // 0
    to_half_kernel<<<(BM_ * DZ / 4 + 255) / 256, 256>>>(z, zr, BM_ * DZ / 4);       // 1
    transpose_half<<<dim3(DD / 32, DD / 32), dim3(32, 8)>>>(Wq, wqT, DD, DD);       // 2
    transpose_half<<<dim3(DD / 32, DZ / 32), dim3(32, 8)>>>(Wk, wkT, DZ, DD);       // 3
    transpose_half<<<dim3(DD / 32, DZ / 32), dim3(32, 8)>>>(Wv, wvT, DZ, DD);       // 4

    gemm_fp16<0><<<(BT / 128) * (DD / 128), 256, SMEM>>>(hn, wqT, bq, qb, BT, DD, DD, nullptr, nullptr);   // 5
    gemm_fp16<0><<<(BM_ / 128) * (DD / 128), 256, SMEM>>>(zr, wkT, bk, kb, BM_, DD, DZ, nullptr, nullptr); // 6
    gemm_fp16<0><<<(BM_ / 128) * (DD / 128), 256, SMEM>>>(zr, wvT, bv, vb, BM_, DD, DZ, nullptr, nullptr); // 7

    transpose_half<<<dim3(DFF / 32, DD / 32), dim3(32, 8)>>>(W1, w1T, DD, DFF);     // 8
    transpose_half<<<dim3(DD / 32, DFF / 32), dim3(32, 8)>>>(W2, w2T, DFF, DD);     // 9

    {
        int smem = (3 * 64 * 128 + 8 * 256) * (int)sizeof(float);
        cudaFuncSetAttribute(attn_kernel, cudaFuncAttributeMaxDynamicSharedMemorySize, smem);
        attn_kernel<<<dim3(TT / 64, HH, BB), 256, smem>>>(qb, kb, vb, cx);          // 10
    }

    gemm_fp16<1><<<(BT / 128) * (DFF / 128), 256, SMEM>>>(cx, w1T, b1, gb, BT, DFF, DD, nullptr, nullptr); // 11
    gemm_fp16<2><<<(BT / 128) * (DD / 128), 256, SMEM>>>(gb, w2T, b2, out, BT, DD, DFF, h, alpha);         // 12
}

// round 6
// speedup vs baseline: 1.5153x; 1.1114x over previous
#include <cuda_runtime.h>
#include <cuda_fp16.h>
#include <math.h>
#include <stdint.h>

// ---------------- problem constants ----------------
#define BB    4
#define TT    4096
#define DD    2048
#define MM    64
#define DZ    512
#define HH    16
#define DH    128
#define DFF   8192
#define BT    (BB*TT)     // 16384
#define BM_   (BB*MM)     // 256

// ---------------- device scratch ----------------
__device__ __half g_hn [BT * DD];
__device__ __half g_z  [BM_ * DZ];
__device__ __half g_WqT[DD * DD];        // [N,K] K-major
__device__ __half g_WkT[DD * DZ];
__device__ __half g_WvT[DD * DZ];
__device__ __half g_W1T[DFF * DD];
__device__ __half g_W2T[DD * DFF];
__device__ __half g_Q  [BT * DD];
__device__ __half g_K  [BM_ * DD];
__device__ __half g_V  [BM_ * DD];
__device__ __half g_ctx[BT * DD];
__device__ __half g_G  [BT * DFF];

// ---------------- helpers ----------------
__device__ __forceinline__ float gelu_exact(float x) {
    return 0.5f * x * (1.f + erff(x * 0.70710678118654752440f));
}
__device__ __forceinline__ void cp_async16(uint32_t s, const void* g) {
    asm volatile("cp.async.cg.shared.global [%0], [%1], 16;" :: "r"(s), "l"(g));
}
__device__ __forceinline__ void cp_commit() {
    asm volatile("cp.async.commit_group;");
}
template<int N> __device__ __forceinline__ void cp_wait() {
    asm volatile("cp.async.wait_group %0;" :: "n"(N));
}
__device__ __forceinline__ void ldsm4(uint32_t& r0, uint32_t& r1, uint32_t& r2, uint32_t& r3,
                                      uint32_t addr) {
    asm volatile("ldmatrix.sync.aligned.m8n8.x4.shared.b16 {%0,%1,%2,%3}, [%4];"
        : "=r"(r0), "=r"(r1), "=r"(r2), "=r"(r3) : "r"(addr));
}
__device__ __forceinline__ void mma16816(float* c,
                                         uint32_t a0, uint32_t a1, uint32_t a2, uint32_t a3,
                                         uint32_t b0, uint32_t b1) {
    asm volatile(
        "mma.sync.aligned.m16n8k16.row.col.f32.f16.f16.f32 "
        "{%0,%1,%2,%3}, {%4,%5,%6,%7}, {%8,%9}, {%0,%1,%2,%3};"
        : "+f"(c[0]), "+f"(c[1]), "+f"(c[2]), "+f"(c[3])
        : "r"(a0), "r"(a1), "r"(a2), "r"(a3), "r"(b0), "r"(b1));
}

// ---------------- elementwise fp32 -> fp16 ----------------
__global__ void to_half_kernel(const float* __restrict__ in, __half* __restrict__ out, int n4) {
    int i = blockIdx.x * blockDim.x + threadIdx.x;
    if (i < n4) {
        float4 v = ((const float4*)in)[i];
        __half2 h0 = __floats2half2_rn(v.x, v.y);
        __half2 h1 = __floats2half2_rn(v.z, v.w);
        uint2 o; o.x = *(uint32_t*)&h0; o.y = *(uint32_t*)&h1;
        ((uint2*)out)[i] = o;
    }
}

// ---------------- weight transpose: W[K,N] fp32 -> Wt[N,K] fp16 ----------------
__global__ __launch_bounds__(256) void transpose_half(
    const float* __restrict__ W, __half* __restrict__ Wt, int K, int N)
{
    __shared__ float t[32][33];
    int n0 = blockIdx.x * 32, k0 = blockIdx.y * 32;
    int tx = threadIdx.x, ty = threadIdx.y;   // 32 x 8
    #pragma unroll
    for (int i = 0; i < 32; i += 8)
        t[ty + i][tx] = W[(size_t)(k0 + ty + i) * N + n0 + tx];
    __syncthreads();
    #pragma unroll
    for (int i = 0; i < 32; i += 8)
        Wt[(size_t)(n0 + ty + i) * K + k0 + tx] = __float2half_rn(t[tx][ty + i]);
}

// ---------------- LayerNorm: fp32 in, fp16 out ----------------
__global__ __launch_bounds__(256) void ln_kernel(
    const float* __restrict__ h, const float* __restrict__ g,
    const float* __restrict__ b, __half* __restrict__ out)
{
    int row = blockIdx.x;
    const float4* x4 = (const float4*)(h + (size_t)row * DD);
    int tx = threadIdx.x;
    float4 v0 = x4[tx], v1 = x4[tx + 256];
    float s  = v0.x + v0.y + v0.z + v0.w + v1.x + v1.y + v1.z + v1.w;
    float s2 = v0.x*v0.x + v0.y*v0.y + v0.z*v0.z + v0.w*v0.w
             + v1.x*v1.x + v1.y*v1.y + v1.z*v1.z + v1.w*v1.w;
    int lane = tx & 31, warp = tx >> 5;
    #pragma unroll
    for (int o = 16; o; o >>= 1) {
        s  += __shfl_xor_sync(0xffffffffu, s,  o);
        s2 += __shfl_xor_sync(0xffffffffu, s2, o);
    }
    __shared__ float sh[16];
    if (lane == 0) { sh[warp] = s; sh[warp + 8] = s2; }
    __syncthreads();
    float ts = 0.f, ts2 = 0.f;
    #pragma unroll
    for (int i = 0; i < 8; i++) { ts += sh[i]; ts2 += sh[i + 8]; }
    float mu  = ts * (1.f / DD);
    float var = ts2 * (1.f / DD) - mu * mu;
    float inv = rsqrtf(var + 1e-5f);

    const float4* g4 = (const float4*)g;
    const float4* b4 = (const float4*)b;
    uint2* o4 = (uint2*)(out + (size_t)row * DD);
    #pragma unroll
    for (int half_i = 0; half_i < 2; half_i++) {
        float4 v = half_i ? v1 : v0;
        int idx = tx + half_i * 256;
        float4 ga = g4[idx], bb = b4[idx];
        float y0 = (v.x - mu) * inv * ga.x + bb.x;
        float y1 = (v.y - mu) * inv * ga.y + bb.y;
        float y2 = (v.z - mu) * inv * ga.z + bb.z;
        float y3 = (v.w - mu) * inv * ga.w + bb.w;
        __half2 h0 = __floats2half2_rn(y0, y1);
        __half2 h1 = __floats2half2_rn(y2, y3);
        uint2 o; o.x = *(uint32_t*)&h0; o.y = *(uint32_t*)&h1;
        o4[idx] = o;
    }
}

// ---------------- fp16 GEMM: C[M,N] = A[M,K] @ Bt[N,K]^T ----------------
// 128x128 tile, 32x64 warp tile, BK=64 (128B rows, full SW128), 3 stages.
template<int EPI>
__global__ void __launch_bounds__(256, 2) gemm_fp16(
    const __half* __restrict__ A, const __half* __restrict__ Bt,
    const float* __restrict__ bias, void* __restrict__ Cv,
    int Mdim, int Ndim, int Kdim,
    const float* __restrict__ res, const float* __restrict__ alpha)
{
    constexpr int STAGE = 32768;
    extern __shared__ __align__(128) char smem[];
    uint32_t sb = (uint32_t)__cvta_generic_to_shared(smem);
    const int tid  = threadIdx.x;
    const int lane = tid & 31, warp = tid >> 5;
    const int wm = (warp & 3) * 32, wn = (warp >> 2) * 64;

    int gm = Mdim >> 7, gn = Ndim >> 7;
    int pid = blockIdx.x;
    const int GRP = 8;
    int width = GRP * gn;
    int grp = pid / width;
    int first = grp * GRP;
    int sz = min(gm - first, GRP);
    int mt = first + (pid % sz);
    int nt = (pid % width) / sz;
    const int bm = mt << 7, bn = nt << 7;

    float acc[2][8][4];
    #pragma unroll
    for (int i = 0; i < 2; i++)
        #pragma unroll
        for (int j = 0; j < 8; j++)
            #pragma unroll
            for (int k = 0; k < 4; k++) acc[i][j][k] = 0.f;

    const int KT = Kdim >> 6;

    const int lrow = tid >> 3, lch = tid & 7;
    auto loadTile = [&](int kt, int st) {
        uint32_t base = sb + st * STAGE;
        const __half* Ag = A  + (size_t)bm * Kdim + kt * 64 + lch * 8;
        const __half* Bg = Bt + (size_t)bn * Kdim + kt * 64 + lch * 8;
        #pragma unroll
        for (int i = 0; i < 4; i++) {
            int r = lrow + i * 32;
            uint32_t sw = (uint32_t)(lch ^ (r & 7)) << 4;
            cp_async16(base + r * 128 + sw,         Ag + (size_t)r * Kdim);
            cp_async16(base + 16384 + r * 128 + sw, Bg + (size_t)r * Kdim);
        }
        cp_commit();
    };

    loadTile(0, 0); loadTile(1, 1);

    const int ar0 = wm + (lane & 15);
    const int brr = wn + (lane & 7) + ((lane >> 4) << 3);
    const int a_l16 = (lane >> 4);
    const int b_l8  = (lane >> 3) & 1;

    int st = 0;
    for (int kt = 0; kt < KT; ++kt) {
        cp_wait<1>();
        __syncthreads();
        if (kt + 2 < KT) {
            int nst = st + 2; if (nst >= 3) nst -= 3;
            loadTile(kt + 2, nst);
        } else {
            cp_commit();
        }

        uint32_t Ab = sb + st * STAGE;
        uint32_t Bb = Ab + 16384;
        #pragma unroll
        for (int ks = 0; ks < 4; ++ks) {
            uint32_t a[2][4];
            int ach = ks * 2 + a_l16;
            #pragma unroll
            for (int mi = 0; mi < 2; mi++) {
                int r = ar0 + mi * 16;
                uint32_t addr = Ab + r * 128 + (((uint32_t)(ach ^ (r & 7))) << 4);
                ldsm4(a[mi][0], a[mi][1], a[mi][2], a[mi][3], addr);
            }
            int bch = ks * 2 + b_l8;
            #pragma unroll
            for (int ni = 0; ni < 4; ni++) {
                int r = brr + ni * 16;
                uint32_t addr = Bb + r * 128 + (((uint32_t)(bch ^ (r & 7))) << 4);
                uint32_t b0, b1, b2, b3;
                ldsm4(b0, b1, b2, b3, addr);
                #pragma unroll
                for (int mi = 0; mi < 2; mi++) {
                    mma16816(acc[mi][ni * 2    ], a[mi][0], a[mi][1], a[mi][2], a[mi][3], b0, b1);
                    mma16816(acc[mi][ni * 2 + 1], a[mi][0], a[mi][1], a[mi][2], a[mi][3], b2, b3);
                }
            }
        }
        if (++st == 3) st = 0;
    }

    float ta = 0.f;
    if (EPI == 2) ta = tanhf(*alpha);
    const int r0 = bm + wm + (lane >> 2);
    const int c0 = bn + wn + (lane & 3) * 2;
    #pragma unroll
    for (int mi = 0; mi < 2; mi++) {
        #pragma unroll
        for (int nj = 0; nj < 8; nj++) {
            int col = c0 + nj * 8;
            float2 bv = *(const float2*)&bias[col];
            #pragma unroll
            for (int hf = 0; hf < 2; hf++) {
                int row = r0 + mi * 16 + hf * 8;
                float v0 = acc[mi][nj][hf * 2    ] + bv.x;
                float v1 = acc[mi][nj][hf * 2 + 1] + bv.y;
                size_t off = (size_t)row * Ndim + col;
                if (EPI == 0) {
                    __half2 hv = __floats2half2_rn(v0, v1);
                    *(__half2*)((__half*)Cv + off) = hv;
                } else if (EPI == 1) {
                    __half2 hv = __floats2half2_rn(gelu_exact(v0), gelu_exact(v1));
                    *(__half2*)((__half*)Cv + off) = hv;
                } else {
                    float2 rr = *(const float2*)&res[off];
                    float2 o; o.x = rr.x + ta * v0; o.y = rr.y + ta * v1;
                    *(float2*)((float*)Cv + off) = o;
                }
            }
        }
    }
}

// ---------------- tensor-core cross-attention ----------------
// Per block: 128 Q rows, one (batch, head). 8 warps x 16 rows.
// S = Q@K^T (128x64x128), softmax, O = P@V (128x128x64). All mma m16n8k16.
// smem: Qs[128][256B sw], Ks[64][256B sw], Vt[128][128B sw] (V transposed), Ps[128][128B sw]
__global__ __launch_bounds__(256, 2) void attn_mma(
    const __half* __restrict__ Q, const __half* __restrict__ Kb,
    const __half* __restrict__ Vb, __half* __restrict__ ctx)
{
    extern __shared__ __align__(128) char smem[];
    uint32_t sb = (uint32_t)__cvta_generic_to_shared(smem);
    const uint32_t QS = 0, KS = 32768, VT = 49152, PS = 65536;

    const int b = blockIdx.z, hh = blockIdx.y;
    const int t0 = blockIdx.x * 128;
    const int tid = threadIdx.x, lane = tid & 31, w = tid >> 5;

    // --- load Q (128x256B) and K (64x256B), cp.async, swizzled per 128B half ---
    {
        int ch = tid & 15, r16 = tid >> 4;
        #pragma unroll
        for (int i = 0; i < 8; i++) {
            int row = r16 + i * 16;
            uint32_t off = row * 256 + ((ch >> 3) << 7) + (((uint32_t)((ch & 7) ^ (row & 7))) << 4);
            cp_async16(sb + QS + off, Q + (size_t)(b * TT + t0 + row) * DD + hh * DH + ch * 8);
        }
        #pragma unroll
        for (int i = 0; i < 4; i++) {
            int row = r16 + i * 16;
            uint32_t off = row * 256 + ((ch >> 3) << 7) + (((uint32_t)((ch & 7) ^ (row & 7))) << 4);
            cp_async16(sb + KS + off, Kb + (size_t)(b * MM + row) * DD + hh * DH + ch * 8);
        }
        cp_commit();
    }
    // --- load V transposed: Vt[d][m], 128 rows x 128B, swizzled ---
    for (int i = tid; i < MM * DH; i += 256) {
        int m = i >> 7, d = i & 127;
        __half v = Vb[(size_t)(b * MM + m) * DD + hh * DH + d];
        uint32_t off = d * 128 + (((uint32_t)((m >> 3) ^ (d & 7))) << 4) + (m & 7) * 2;
        *(__half*)(smem + VT + off) = v;
    }
    cp_wait<0>();
    __syncthreads();

    const int arow = w * 16 + (lane & 15);
    const int a_hi = lane >> 4;
    const int brow = (lane & 7) + ((lane >> 4) << 3);
    const int b_l8 = (lane >> 3) & 1;

    // --- S = Q @ K^T ---
    float sacc[8][4];
    #pragma unroll
    for (int i = 0; i < 8; i++)
        #pragma unroll
        for (int j = 0; j < 4; j++) sacc[i][j] = 0.f;

    #pragma unroll
    for (int ks = 0; ks < 8; ++ks) {
        int ach = ks * 2 + a_hi;
        uint32_t aaddr = sb + QS + arow * 256 + ((ach >> 3) << 7)
                       + (((uint32_t)((ach & 7) ^ (arow & 7))) << 4);
        uint32_t a0, a1, a2, a3;
        ldsm4(a0, a1, a2, a3, aaddr);
        int bch = ks * 2 + b_l8;
        #pragma unroll
        for (int ni = 0; ni < 4; ++ni) {
            int r = brow + ni * 16;
            uint32_t baddr = sb + KS + r * 256 + ((bch >> 3) << 7)
                           + (((uint32_t)((bch & 7) ^ (r & 7))) << 4);
            uint32_t b0, b1, b2, b3;
            ldsm4(b0, b1, b2, b3, baddr);
            mma16816(sacc[ni * 2    ], a0, a1, a2, a3, b0, b1);
            mma16816(sacc[ni * 2 + 1], a0, a1, a2, a3, b2, b3);
        }
    }

    // --- softmax (rows lane>>2 and +8 of this warp's 16) ---
    const float scale = 0.08838834764831844f;
    float mxA = -1e30f, mxB = -1e30f;
    #pragma unroll
    for (int nj = 0; nj < 8; nj++) {
        sacc[nj][0] *= scale; sacc[nj][1] *= scale;
        sacc[nj][2] *= scale; sacc[nj][3] *= scale;
        mxA = fmaxf(mxA, fmaxf(sacc[nj][0], sacc[nj][1]));
        mxB = fmaxf(mxB, fmaxf(sacc[nj][2], sacc[nj][3]));
    }
    mxA = fmaxf(mxA, __shfl_xor_sync(0xffffffffu, mxA, 1));
    mxA = fmaxf(mxA, __shfl_xor_sync(0xffffffffu, mxA, 2));
    mxB = fmaxf(mxB, __shfl_xor_sync(0xffffffffu, mxB, 1));
    mxB = fmaxf(mxB, __shfl_xor_sync(0xffffffffu, mxB, 2));

    const int prA = w * 16 + (lane >> 2);
    const int prB = prA + 8;
    float smA = 0.f, smB = 0.f;
    #pragma unroll
    for (int nj = 0; nj < 8; nj++) {
        float e0 = expf(sacc[nj][0] - mxA), e1 = expf(sacc[nj][1] - mxA);
        float e2 = expf(sacc[nj][2] - mxB), e3 = expf(sacc[nj][3] - mxB);
        smA += e0 + e1; smB += e2 + e3;
        __half2 hA = __floats2half2_rn(e0, e1);
        __half2 hB = __floats2half2_rn(e2, e3);
        uint32_t offA = prA * 128 + (((uint32_t)(nj ^ (prA & 7))) << 4) + (lane & 3) * 4;
        uint32_t offB = prB * 128 + (((uint32_t)(nj ^ (prB & 7))) << 4) + (lane & 3) * 4;
        *(__half2*)(smem + PS + offA) = hA;
        *(__half2*)(smem + PS + offB) = hB;
    }
    smA += __shfl_xor_sync(0xffffffffu, smA, 1);
    smA += __shfl_xor_sync(0xffffffffu, smA, 2);
    smB += __shfl_xor_sync(0xffffffffu, smB, 1);
    smB += __shfl_xor_sync(0xffffffffu, smB, 2);
    __syncwarp();

    // --- O = P @ V  (A = Ps rows of this warp, B = Vt) ---
    float oacc[16][4];
    #pragma unroll
    for (int i = 0; i < 16; i++)
        #pragma unroll
        for (int j = 0; j < 4; j++) oacc[i][j] = 0.f;

    #pragma unroll
    for (int ks = 0; ks < 4; ++ks) {
        int ach = ks * 2 + a_hi;
        uint32_t aaddr = sb + PS + arow * 128 + (((uint32_t)(ach ^ (arow & 7))) << 4);
        uint32_t a0, a1, a2, a3;
        ldsm4(a0, a1, a2, a3, aaddr);
        int bch = ks * 2 + b_l8;
        #pragma unroll
        for (int ni = 0; ni < 8; ++ni) {
            int r = brow + ni * 16;
            uint32_t baddr = sb + VT + r * 128 + (((uint32_t)(bch ^ (r & 7))) << 4);
            uint32_t b0, b1, b2, b3;
            ldsm4(b0, b1, b2, b3, baddr);
            mma16816(oacc[ni * 2    ], a0, a1, a2, a3, b0, b1);
            mma16816(oacc[ni * 2 + 1], a0, a1, a2, a3, b2, b3);
        }
    }

    // --- write ctx, normalized by row sums ---
    float invA = 1.f / smA, invB = 1.f / smB;
    const size_t rowAoff = (size_t)(b * TT + t0 + prA) * DD + hh * DH;
    const size_t rowBoff = (size_t)(b * TT + t0 + prB) * DD + hh * DH;
    const int cbase = (lane & 3) * 2;
    #pragma unroll
    for (int nj = 0; nj < 16; nj++) {
        int col = cbase + nj * 8;
        __half2 hA = __floats2half2_rn(oacc[nj][0] * invA, oacc[nj][1] * invA);
        __half2 hB = __floats2half2_rn(oacc[nj][2] * invB, oacc[nj][3] * invB);
        *(__half2*)&ctx[rowAoff + col] = hA;
        *(__half2*)&ctx[rowBoff + col] = hB;
    }
}

// ---------------- launch ----------------
template<typename T>
static T* sym_addr(const void* sym) {
    void* p = nullptr;
    cudaGetSymbolAddress(&p, sym);
    return (T*)p;
}

extern "C" void kernel_launch(void* const* d_in, const int* in_sizes, int n_in,
                              void* d_out, int out_size)
{
    const float* h    = (const float*)d_in[0];
    const float* z    = (const float*)d_in[1];
    const float* ln_g = (const float*)d_in[2];
    const float* ln_b = (const float*)d_in[3];
    const float* Wq   = (const float*)d_in[4];
    const float* bq   = (const float*)d_in[5];
    const float* Wk   = (const float*)d_in[6];
    const float* bk   = (const float*)d_in[7];
    const float* Wv   = (const float*)d_in[8];
    const float* bv   = (const float*)d_in[9];
    const float* W1   = (const float*)d_in[10];
    const float* b1   = (const float*)d_in[11];
    const float* W2   = (const float*)d_in[12];
    const float* b2   = (const float*)d_in[13];
    const float* alpha= (const float*)d_in[14];
    float* out = (float*)d_out;

    __half* hn  = sym_addr<__half>(g_hn);
    __half* zr  = sym_addr<__half>(g_z);
    __half* wqT = sym_addr<__half>(g_WqT);
    __half* wkT = sym_addr<__half>(g_WkT);
    __half* wvT = sym_addr<__half>(g_WvT);
    __half* w1T = sym_addr<__half>(g_W1T);
    __half* w2T = sym_addr<__half>(g_W2T);
    __half* qb  = sym_addr<__half>(g_Q);
    __half* kb  = sym_addr<__half>(g_K);
    __half* vb  = sym_addr<__half>(g_V);
    __half* cx  = sym_addr<__half>(g_ctx);
    __half* gb  = sym_addr<__half>(g_G);

    const int SMEM = 3 * 32768;   // 96KB, 2 CTA/SM
    cudaFuncSetAttribute(gemm_fp16<0>, cudaFuncAttributeMaxDynamicSharedMemorySize, SMEM);
    cudaFuncSetAttribute(gemm_fp16<1>, cudaFuncAttributeMaxDynamicSharedMemorySize, SMEM);
    cudaFuncSetAttribute(gemm_fp16<2>, cudaFuncAttributeMaxDynamicSharedMemorySize, SMEM);
    const int ASM = 81920;        // 80KB attn smem, 2 CTA/SM
    cudaFuncSetAttribute(attn_mma, cudaFuncAttributeMaxDynamicSharedMemorySize, ASM);

    // launch order: index 3 = Q-projection GEMM (ncu capture lands on index 3)
    ln_kernel<<<BT, 256>>>(h, ln_g, ln_b, hn);                                      // 0
    transpose_half<<<dim3(DD / 32, DD / 32), dim3(32, 8)>>>(Wq, wqT, DD, DD);       // 1
    to_half_kernel<<<(BM_ * DZ / 4 + 255) / 256, 256>>>(z, zr, BM_ * DZ / 4);       // 2
    gemm_fp16<0><<<(BT / 128) * (DD / 128), 256, SMEM>>>(hn, wqT, bq, qb, BT, DD, DD, nullptr, nullptr);   // 3
    transpose_half<<<dim3(DD / 32, DZ / 32), dim3(32, 8)>>>(Wk, wkT, DZ, DD);       // 4
    transpose_half<<<dim3(DD / 32, DZ / 32), dim3(32, 8)>>>(Wv, wvT, DZ, DD);       // 5
    gemm_fp16<0><<<(BM_ / 128) * (DD / 128), 256, SMEM>>>(zr, wkT, bk, kb, BM_, DD, DZ, nullptr, nullptr); // 6
    gemm_fp16<0><<<(BM_ / 128) * (DD / 128), 256, SMEM>>>(zr, wvT, bv, vb, BM_, DD, DZ, nullptr, nullptr); // 7
    transpose_half<<<dim3(DFF / 32, DD / 32), dim3(32, 8)>>>(W1, w1T, DD, DFF);     // 8
    transpose_half<<<dim3(DD / 32, DFF / 32), dim3(32, 8)>>>(W2, w2T, DFF, DD);     // 9

    attn_mma<<<dim3(TT / 128, HH, BB), 256, ASM>>>(qb, kb, vb, cx);                 // 10

    gemm_fp16<1><<<(BT / 128) * (DFF / 128), 256, SMEM>>>(cx, w1T, b1, gb, BT, DFF, DD, nullptr, nullptr); // 11
    gemm_fp16<2><<<(BT / 128) * (DD / 128), 256, SMEM>>>(gb, w2T, b2, out, BT, DD, DFF, h, alpha);         // 12
}